// round 3
// baseline (speedup 1.0000x reference)
#include <cuda_runtime.h>
#include <cstdint>

#define MDIM 8192
#define KDIM 8192
#define NDIM 8192

#define ROW_TILES 148   // one row-tile per SM-resident block slot
#define COL_TILES 8     // 8 * 256 threads * float4 = 8192 columns

// ---- scratch (device globals; no allocation allowed) ----
__device__ float g_partial[ROW_TILES * KDIM]; // 4.6 MiB, overwritten each launch
__device__ float g_wcs[KDIM];                 // 32 KiB column-sum of W

// ============================================================
// Kernel 1: partial column sums of W.
// Grid: exactly COL_TILES * ROW_TILES = 1184 blocks = 8 per SM
// (32 regs, 256 thr -> 8 blocks/SM = 100% occupancy, one balanced wave).
// Block b owns col-tile (b & 7) and row set { (b>>3) + 148*i }.
// Deterministic: exclusive ownership, plain stores.
// ============================================================
__global__ __launch_bounds__(256, 8) void colsum_partial(const float* __restrict__ w) {
    const int bid  = blockIdx.x;
    const int col4 = (bid & (COL_TILES - 1)) * 256 + threadIdx.x; // float4 idx in row
    const int rt   = bid >> 3;                                    // 0..147

    const float4* wp = reinterpret_cast<const float4*>(w) + col4;

    float4 acc = make_float4(0.f, 0.f, 0.f, 0.f);
    // rows rt, rt+148, rt+296, ... (~55 rows per block)
    #pragma unroll 4
    for (int r = rt; r < NDIM; r += ROW_TILES) {
        float4 v = __ldcs(wp + (size_t)r * (KDIM / 4)); // one-touch: evict-first
        acc.x += v.x; acc.y += v.y; acc.z += v.z; acc.w += v.w;
    }
    reinterpret_cast<float4*>(g_partial)[(size_t)rt * (KDIM / 4) + col4] = acc;
}

// ============================================================
// Kernel 2: fold the 148 partials -> g_wcs (4.6 MiB read).
// ============================================================
__global__ __launch_bounds__(256) void colsum_reduce() {
    const int k = blockIdx.x * 256 + threadIdx.x; // column index
    float s = 0.f;
    #pragma unroll 4
    for (int rt = 0; rt < ROW_TILES; ++rt)
        s += g_partial[(size_t)rt * KDIM + k];
    g_wcs[k] = s;
}

// ============================================================
// Kernel 3: y[m] = 0.75 * dot(x[m,:], wcs).
// Warp-per-row: 8 warps/block -> 1024 blocks. Pure shuffle
// reduction, no smem, no __syncthreads. wcs (32 KiB) is
// L1/L2-resident and shared by all 8 warps of a block.
// ============================================================
__global__ __launch_bounds__(256, 8) void rowdot(const float* __restrict__ x,
                                                 float* __restrict__ y) {
    const int warp = threadIdx.x >> 5;
    const int lane = threadIdx.x & 31;
    const int row  = blockIdx.x * 8 + warp;

    const float4* xp = reinterpret_cast<const float4*>(x) + (size_t)row * (KDIM / 4);
    const float4* wp = reinterpret_cast<const float4*>(g_wcs);

    float4 acc = make_float4(0.f, 0.f, 0.f, 0.f);
    // 2048 float4 per row / 32 lanes = 64 iters per lane
    #pragma unroll 8
    for (int i = lane; i < KDIM / 4; i += 32) {
        float4 a = __ldcs(xp + i);  // one-touch: evict-first
        float4 b = __ldg(wp + i);   // hot: L1-resident
        acc.x += a.x * b.x;
        acc.y += a.y * b.y;
        acc.z += a.z * b.z;
        acc.w += a.w * b.w;
    }
    float s = (acc.x + acc.y) + (acc.z + acc.w);

    #pragma unroll
    for (int off = 16; off > 0; off >>= 1)
        s += __shfl_xor_sync(0xFFFFFFFFu, s, off);

    if (lane == 0) y[row] = 0.75f * s;
}

extern "C" void kernel_launch(void* const* d_in, const int* in_sizes, int n_in,
                              void* d_out, int out_size) {
    const float* x = (const float*)d_in[0];  // [M, K]
    const float* w = (const float*)d_in[1];  // [N, K]
    float* y = (float*)d_out;                // [M, 1]

    colsum_partial<<<COL_TILES * ROW_TILES, 256>>>(w);
    colsum_reduce<<<KDIM / 256, 256>>>();
    rowdot<<<MDIM / 8, 256>>>(x, y);
}

// round 4
// speedup vs baseline: 1.0765x; 1.0765x over previous
#include <cuda_runtime.h>
#include <cstdint>

#define MDIM 8192
#define KDIM 8192
#define NDIM 8192

#define ROW_TILES 148   // one row-tile per SM-resident block slot
#define COL_TILES 8     // 8 * 256 threads * float4 = 8192 columns

// ---- scratch (device globals; no allocation allowed) ----
__device__ float g_partial[ROW_TILES * KDIM]; // 4.6 MiB, overwritten each launch
__device__ float g_wcs[KDIM];                 // 32 KiB column-sum of W

// ============================================================
// Kernel 1: partial column sums of W. (R3 version: proven 41.6us)
// Grid: exactly COL_TILES * ROW_TILES = 1184 blocks = 8 per SM.
// ============================================================
__global__ __launch_bounds__(256, 8) void colsum_partial(const float* __restrict__ w) {
    const int bid  = blockIdx.x;
    const int col4 = (bid & (COL_TILES - 1)) * 256 + threadIdx.x;
    const int rt   = bid >> 3;

    const float4* wp = reinterpret_cast<const float4*>(w) + col4;

    float4 acc = make_float4(0.f, 0.f, 0.f, 0.f);
    #pragma unroll 4
    for (int r = rt; r < NDIM; r += ROW_TILES) {
        float4 v = __ldcs(wp + (size_t)r * (KDIM / 4));
        acc.x += v.x; acc.y += v.y; acc.z += v.z; acc.w += v.w;
    }
    reinterpret_cast<float4*>(g_partial)[(size_t)rt * (KDIM / 4) + col4] = acc;
}

// ============================================================
// Kernel 2: fold the 148 partials -> g_wcs (4.6 MiB read).
// ============================================================
__global__ __launch_bounds__(256) void colsum_reduce() {
    const int k = blockIdx.x * 256 + threadIdx.x;
    float s = 0.f;
    #pragma unroll 4
    for (int rt = 0; rt < ROW_TILES; ++rt)
        s += g_partial[(size_t)rt * KDIM + k];
    g_wcs[k] = s;
}

// ============================================================
// Kernel 3: y[m] = 0.75 * dot(x[m,:], wcs).
// 4 rows per block; each thread's wcs slice (8 float4) loaded
// ONCE into registers and reused across the 4 rows -> wcs L2
// traffic cut 4x. Per row: 8 fully-unrolled independent
// LDG.128 (the R2-proven high-MLP pattern).
// ============================================================
#define ROWS_PER_BLK 4
__global__ __launch_bounds__(256) void rowdot(const float* __restrict__ x,
                                              float* __restrict__ y) {
    const int tid  = threadIdx.x;
    const int row0 = blockIdx.x * ROWS_PER_BLK;
    const float4* wp = reinterpret_cast<const float4*>(g_wcs);

    // cache this thread's wcs slice in registers (coalesced loads)
    float4 wreg[8];
    #pragma unroll
    for (int j = 0; j < 8; ++j)
        wreg[j] = __ldg(wp + tid + 256 * j);

    float acc[ROWS_PER_BLK];
    #pragma unroll
    for (int r = 0; r < ROWS_PER_BLK; ++r) {
        const float4* xp = reinterpret_cast<const float4*>(x)
                         + (size_t)(row0 + r) * (KDIM / 4);
        float s = 0.f;
        #pragma unroll
        for (int j = 0; j < 8; ++j) {
            float4 a = __ldcs(xp + tid + 256 * j);  // one-touch streaming
            s += a.x * wreg[j].x + a.y * wreg[j].y
               + a.z * wreg[j].z + a.w * wreg[j].w;
        }
        acc[r] = s;
    }

    // block-wide reduction of the 4 row sums
    const int warp = tid >> 5;
    const int lane = tid & 31;
    __shared__ float red[8][ROWS_PER_BLK];

    #pragma unroll
    for (int r = 0; r < ROWS_PER_BLK; ++r) {
        float s = acc[r];
        #pragma unroll
        for (int off = 16; off > 0; off >>= 1)
            s += __shfl_xor_sync(0xFFFFFFFFu, s, off);
        if (lane == 0) red[warp][r] = s;
    }
    __syncthreads();

    if (warp == 0 && lane < 8) {
        #pragma unroll
        for (int r = 0; r < ROWS_PER_BLK; ++r) {
            float t = red[lane][r];
            #pragma unroll
            for (int off = 4; off > 0; off >>= 1)
                t += __shfl_xor_sync(0xFFu, t, off);
            if (lane == 0) y[row0 + r] = 0.75f * t;
        }
    }
}

extern "C" void kernel_launch(void* const* d_in, const int* in_sizes, int n_in,
                              void* d_out, int out_size) {
    const float* x = (const float*)d_in[0];  // [M, K]
    const float* w = (const float*)d_in[1];  // [N, K]
    float* y = (float*)d_out;                // [M, 1]

    colsum_partial<<<COL_TILES * ROW_TILES, 256>>>(w);
    colsum_reduce<<<KDIM / 256, 256>>>();
    rowdot<<<MDIM / ROWS_PER_BLK, 256>>>(x, y);
}

// round 5
// speedup vs baseline: 1.0902x; 1.0126x over previous
#include <cuda_runtime.h>
#include <cstdint>

#define MDIM 8192
#define KDIM 8192
#define NDIM 8192

#define ROW_TILES 148   // one row-tile per SM-resident block slot
#define COL_TILES 8     // 8 * 256 threads * float4 = 8192 columns

// ---- scratch (device globals; no allocation allowed) ----
__device__ float g_partial[ROW_TILES * KDIM]; // 4.6 MiB, overwritten each launch
__device__ float g_wcs[KDIM];                 // 32 KiB column-sum of W

// ============================================================
// Kernel 1: partial column sums of W. (proven: 41.0us, 6.64 TB/s)
// Grid: exactly COL_TILES * ROW_TILES = 1184 blocks = 8 per SM.
// ============================================================
__global__ __launch_bounds__(256, 8) void colsum_partial(const float* __restrict__ w) {
    const int bid  = blockIdx.x;
    const int col4 = (bid & (COL_TILES - 1)) * 256 + threadIdx.x;
    const int rt   = bid >> 3;

    const float4* wp = reinterpret_cast<const float4*>(w) + col4;

    float4 acc = make_float4(0.f, 0.f, 0.f, 0.f);
    #pragma unroll 4
    for (int r = rt; r < NDIM; r += ROW_TILES) {
        float4 v = __ldcs(wp + (size_t)r * (KDIM / 4));
        acc.x += v.x; acc.y += v.y; acc.z += v.z; acc.w += v.w;
    }
    reinterpret_cast<float4*>(g_partial)[(size_t)rt * (KDIM / 4) + col4] = acc;
}

// ============================================================
// Kernel 2: fold the 148 partials -> g_wcs (4.6 MiB read).
// ============================================================
__global__ __launch_bounds__(256) void colsum_reduce() {
    const int k = blockIdx.x * 256 + threadIdx.x;
    float s = 0.f;
    #pragma unroll 4
    for (int rt = 0; rt < ROW_TILES; ++rt)
        s += g_partial[(size_t)rt * KDIM + k];
    g_wcs[k] = s;
}

// ============================================================
// Kernel 3: y[m] = 0.75 * dot(x[m,:], wcs). EXACT R2 version
// (proven ~42us): one 256-thread block per row, stride-256
// unroll-8 loop, shuffle+smem block reduce.
// ============================================================
__global__ __launch_bounds__(256) void rowdot(const float* __restrict__ x,
                                              float* __restrict__ y) {
    const int row = blockIdx.x;
    const int tid = threadIdx.x;
    const float4* xp = reinterpret_cast<const float4*>(x) + (size_t)row * (KDIM / 4);
    const float4* wp = reinterpret_cast<const float4*>(g_wcs);

    float4 acc = make_float4(0.f, 0.f, 0.f, 0.f);
    #pragma unroll 8
    for (int i = tid; i < KDIM / 4; i += 256) {
        float4 a = __ldcs(xp + i);   // one-touch: evict-first
        float4 b = wp[i];            // hot: stays in L2/L1
        acc.x += a.x * b.x;
        acc.y += a.y * b.y;
        acc.z += a.z * b.z;
        acc.w += a.w * b.w;
    }
    float s = (acc.x + acc.y) + (acc.z + acc.w);

    // warp reduce
    #pragma unroll
    for (int off = 16; off > 0; off >>= 1)
        s += __shfl_xor_sync(0xFFFFFFFFu, s, off);

    __shared__ float red[8];
    if ((tid & 31) == 0) red[tid >> 5] = s;
    __syncthreads();
    if (tid < 8) {
        float t = red[tid];
        #pragma unroll
        for (int off = 4; off > 0; off >>= 1)
            t += __shfl_xor_sync(0xFFu, t, off);
        if (tid == 0) y[row] = 0.75f * t;
    }
}

extern "C" void kernel_launch(void* const* d_in, const int* in_sizes, int n_in,
                              void* d_out, int out_size) {
    const float* x = (const float*)d_in[0];  // [M, K]
    const float* w = (const float*)d_in[1];  // [N, K]
    float* y = (float*)d_out;                // [M, 1]

    colsum_partial<<<COL_TILES * ROW_TILES, 256>>>(w);
    colsum_reduce<<<KDIM / 256, 256>>>();
    rowdot<<<MDIM, 256>>>(x, y);
}